// round 16
// baseline (speedup 1.0000x reference)
#include <cuda_runtime.h>
#include <cuda_fp16.h>
#include <float.h>
#include <math.h>

#define CCH 128
#define HWF 409600   // 640*640
#define WF 640
#define HF 640
#define NTPB (HWF / 64)   // 6400 transpose blocks (64 pixels each)
#define NMAX 20000
#define CPB 64            // points per corr2 block

// Slot permutation: slot s holds channel c(s) = (s&3)*32 + (s>>2); s(o) = 4*(o&31)+(o>>5)
__device__ __align__(16) __half d_Msp[CCH * CCH];   // Msp[s_in*128+s_out]
__device__ __align__(16) float  d_up[CCH];
__device__ __align__(16) __half d_f1t[(size_t)HWF * CCH];   // [pixel][slot]
__device__ __align__(16) float  d_r0[NMAX * CCH];           // [n][slot]

// packed fp32x2 FMA (Blackwell)
#define FMA_F32X2(d, a, b, c) \
    asm("fma.rn.f32x2 %0, %1, %2, %3;" : "=l"(d) : "l"(a), "l"(b), "l"(c))

__device__ __forceinline__ unsigned long long pack_f32x2(float lo, float hi) {
    unsigned long long r;
    unsigned ulo = __float_as_uint(lo), uhi = __float_as_uint(hi);
    asm("mov.b64 %0, {%1, %2};" : "=l"(r) : "r"(ulo), "r"(uhi));
    return r;
}
__device__ __forceinline__ void unpack_f32x2(unsigned long long v, float& lo, float& hi) {
    unsigned ulo, uhi;
    asm("mov.b64 {%0, %1}, %2;" : "=r"(ulo), "=r"(uhi) : "l"(v));
    lo = __uint_as_float(ulo);
    hi = __uint_as_float(uhi);
}

// ---------------------------------------------------------------------------
// Kernel 1 "prep": three roles by block index (unchanged from R12/R13).
__global__ void __launch_bounds__(256)
prep_kernel(const float* __restrict__ f1,
            const float* __restrict__ W, const float* __restrict__ b,
            const float* __restrict__ mk0, const float* __restrict__ f0,
            const int* __restrict__ stride_ptr, int N)
{
    __shared__ float wcol[CCH];
    const int blk = blockIdx.x;
    const int t = threadIdx.x;
    const int w = t >> 5, l = t & 31;

    if (blk < 128) {
        const int o = blk;
        if (t < CCH) wcol[t] = W[t * CCH + o];
        __syncthreads();
        if (t < CCH) {
            float acc = 0.f;
#pragma unroll 8
            for (int k = 0; k < CCH; k++) acc += wcol[k] * W[k * CCH + t];
            const int so = 4 * (o & 31) + (o >> 5);
            const int st = 4 * (t & 31) + (t >> 5);
            d_Msp[so * CCH + st] = __float2half(acc);   // symmetric
            if (t == 0) {
                float uu = 0.f;
                for (int k = 0; k < CCH; k++) uu += wcol[k] * b[k];
                d_up[so] = uu;
            }
        }
        return;
    }

    const int r = blk - 128;
    const int grp = r / 7, sub = r % 7;

    if (sub < 5) {
        // transpose role: 64 pixels; lane = 2 pixels, warp = 16 slots
        const int tidx = grp * 5 + sub;
        if (tidx >= NTPB) return;
        const int p0 = tidx * 64 + 2 * l;
        float2 v[16];
#pragma unroll
        for (int d = 0; d < 16; d++) {
            const int c = 4 * w + (d >> 2) + 32 * (d & 3);
            v[d] = __ldg((const float2*)(f1 + (size_t)c * HWF + p0));
        }
#pragma unroll
        for (int j2 = 0; j2 < 2; j2++) {
            unsigned q[8];
#pragma unroll
            for (int d = 0; d < 8; d++) {
                const float a  = j2 ? v[2 * d].y     : v[2 * d].x;
                const float bq = j2 ? v[2 * d + 1].y : v[2 * d + 1].x;
                __half2 h = __floats2half2_rn(a, bq);
                q[d] = *reinterpret_cast<unsigned*>(&h);
            }
            __half* dst = d_f1t + (size_t)(p0 + j2) * CCH + 16 * w;
            *reinterpret_cast<uint4*>(dst)     = make_uint4(q[0], q[1], q[2], q[3]);
            *reinterpret_cast<uint4*>(dst + 8) = make_uint4(q[4], q[5], q[6], q[7]);
        }
        return;
    }

    // gather role: 8 points (one per warp), lane loads 4 channels
    {
        const int gidx = grp * 2 + (sub - 5);
        const int n = gidx * 8 + w;
        if (n >= N) return;
        const int stride = stride_ptr ? __ldg(stride_ptr) : 8;
        const int fr = stride >> 1;
        const float m0x = __ldg(&mk0[2 * n]), m0y = __ldg(&mk0[2 * n + 1]);
        const int cx0 = (int)(m0x * (float)fr), cy0 = (int)(m0y * (float)fr);
        const int cx0c = min(max(cx0, 2), WF - 3), cy0c = min(max(cy0, 2), HF - 3);
        const int pix0 = cy0c * WF + cx0c;
        float v0 = __ldg(f0 + (size_t)(l      ) * HWF + pix0);
        float v1 = __ldg(f0 + (size_t)(l + 32 ) * HWF + pix0);
        float v2 = __ldg(f0 + (size_t)(l + 64 ) * HWF + pix0);
        float v3 = __ldg(f0 + (size_t)(l + 96 ) * HWF + pix0);
        *(float4*)&d_r0[(size_t)n * CCH + 4 * l] = make_float4(v0, v1, v2, v3);
    }
}

// ---------------------------------------------------------------------------
// Kernel 2 "corr2": 512 threads, 64 points/block. Stage Msp once (33KB fp16,
// 313 blocks -> 10MB total staging), matvec g=Msp*r0+up into smem, then
// 16 warps x 4 points of 5x5 patch correlation + softmax + outputs.
// ALL 32 lanes load in the patch loop (lane carries slots 4l..4l+3).
#define R0GPITCH 66
#define C2_SMEM 68096
__global__ void __launch_bounds__(512)
corr2_kernel(const float* __restrict__ mk0, const float* __restrict__ mk1,
             const int* __restrict__ stride_ptr, float* __restrict__ out, int N)
{
    extern __shared__ char smraw[];
    __half* Msh = (__half*)smraw;
    float*  r0g = (float*)(smraw + 32768);
    float*  gsh = r0g;                       // reused after matvec
    float*  ush = (float*)(smraw + 66560);
    int*    hP  = (int*)(smraw + 67072);
    int*    hV  = (int*)(smraw + 67328);
    float*  hX  = (float*)(smraw + 67584);
    float*  hY  = (float*)(smraw + 67840);

    const int t = threadIdx.x;
    const int n0blk = blockIdx.x * CPB;
    const int stride = stride_ptr ? __ldg(stride_ptr) : 8;
    const int fr = stride >> 1;
    const float scalef = (float)(stride / fr);
    const float halfstr = (float)(stride >> 1);

    // ---- stage Msp + up: 2048 uint4 across 512 threads = 4 iterations ----
    {
        const uint4* Ms = (const uint4*)d_Msp;
        uint4* Md = (uint4*)Msh;
#pragma unroll
        for (int i = 0; i < 4; i++) Md[i * 512 + t] = __ldg(&Ms[i * 512 + t]);
        if (t < CCH) ush[t] = d_up[t];
    }

    // ---- header: 64 points ----
    if (t < CPB) {
        const int n = min(n0blk + t, N - 1);
        const float m0x = __ldg(&mk0[2 * n]), m0y = __ldg(&mk0[2 * n + 1]);
        const float m1x = __ldg(&mk1[2 * n]), m1y = __ldg(&mk1[2 * n + 1]);
        const int cx0 = (int)(m0x * (float)fr), cy0 = (int)(m0y * (float)fr);
        const int cx1 = (int)(m1x * (float)fr), cy1 = (int)(m1y * (float)fr);
        const int v = (cx0 >= 2 && cx0 + 2 < WF && cy0 >= 2 && cy0 + 2 < HF &&
                       cx1 >= 2 && cx1 + 2 < WF && cy1 >= 2 && cy1 + 2 < HF);
        const int cx1c = min(max(cx1, 2), WF - 3), cy1c = min(max(cy1, 2), HF - 3);
        hP[t] = cy1c * WF + cx1c;
        hV[t] = v;
        hX[t] = m1x * (float)stride + halfstr;
        hY[t] = m1y * (float)stride + halfstr;
        if (n0blk + t < N) {
            out[2 * n]     = m0x * (float)stride + halfstr;  // pts0
            out[2 * n + 1] = m0y * (float)stride + halfstr;
        }
    }

    // ---- stage r0 (dense, coalesced): r0g[o*66 + q] ----
#pragma unroll
    for (int i = 0; i < 16; i++) {
        const int idx = i * 512 + t;
        const int q = idx >> 7, o = idx & 127;
        const int nc = min(n0blk + q, N - 1);
        r0g[o * R0GPITCH + q] = __ldg(&d_r0[(size_t)nc * CCH + o]);
    }
    __syncthreads();

    // ---- matvec: grp (t>>7) handles points qb..qb+15 for output slot o ----
    const int o = t & 127;
    const int qb = (t >> 7) * 16;
    float gv[16];
    {
        const float uo = ush[o];
        unsigned long long acc[8];
#pragma unroll
        for (int k = 0; k < 8; k++) acc[k] = pack_f32x2(uo, uo);
#pragma unroll 4
        for (int c = 0; c < CCH; c++) {
            const float m = __half2float(Msh[c * CCH + o]);   // Msp[s_in=c][s_out=o]
            const unsigned long long m2 = pack_f32x2(m, m);
            const unsigned long long* rp =
                (const unsigned long long*)&r0g[c * R0GPITCH + qb];
#pragma unroll
            for (int k = 0; k < 8; k++) FMA_F32X2(acc[k], m2, rp[k], acc[k]);
        }
#pragma unroll
        for (int k = 0; k < 8; k++) unpack_f32x2(acc[k], gv[2 * k], gv[2 * k + 1]);
    }
    __syncthreads();   // all r0g reads done
#pragma unroll
    for (int k = 0; k < 16; k++) gsh[(qb + k) * CCH + o] = gv[k];
    __syncthreads();

    // ---- corr: warp w handles points 4w..4w+3 ----
    const int wid = t >> 5, lane = t & 31;
    const bool inpatch = lane < 25;
    const int dx = lane % 5 - 2;
    const int dy = lane / 5 - 2;

#pragma unroll
    for (int j = 0; j < 4; j++) {
        const int q = 4 * wid + j;
        const int n = n0blk + q;
        if (n >= N) break;

        const size_t pixb = (size_t)hP[q];
        const float4 g4 = *(const float4*)&gsh[q * CCH + lane * 4];

        float corr = -FLT_MAX;
#pragma unroll
        for (int row = 0; row < 5; row++) {
            // ALL lanes load: lane carries slots 4*lane..4*lane+3 of each pixel
            const size_t rb = (pixb + (size_t)(row - 2) * WF - 2) * CCH + lane * 4;
            float r[5];
#pragma unroll
            for (int col = 0; col < 5; col++) {
                uint2 u = __ldg((const uint2*)(d_f1t + rb + (size_t)col * CCH));
                __half2 h0 = *reinterpret_cast<__half2*>(&u.x);
                __half2 h1 = *reinterpret_cast<__half2*>(&u.y);
                float2 f01 = __half22float2(h0);
                float2 f23 = __half22float2(h1);
                r[col] = g4.x * f01.x + g4.y * f01.y + g4.z * f23.x + g4.w * f23.y;
            }
#pragma unroll
            for (int d = 16; d; d >>= 1) {
                r[0] += __shfl_xor_sync(0xffffffffu, r[0], d);
                r[1] += __shfl_xor_sync(0xffffffffu, r[1], d);
                r[2] += __shfl_xor_sync(0xffffffffu, r[2], d);
                r[3] += __shfl_xor_sync(0xffffffffu, r[3], d);
                r[4] += __shfl_xor_sync(0xffffffffu, r[4], d);
            }
            const int p0 = row * 5;
#pragma unroll
            for (int col = 0; col < 5; col++)
                if (lane == p0 + col) corr = r[col];
        }

        float cm = corr;
#pragma unroll
        for (int d = 16; d; d >>= 1)
            cm = fmaxf(cm, __shfl_xor_sync(0xffffffffu, cm, d));
        float e  = inpatch ? __expf(corr - cm) : 0.f;
        float ex = e * (float)dx;
        float ey = e * (float)dy;
        float s  = e;
#pragma unroll
        for (int d = 16; d; d >>= 1) {
            s  += __shfl_xor_sync(0xffffffffu, s,  d);
            ex += __shfl_xor_sync(0xffffffffu, ex, d);
            ey += __shfl_xor_sync(0xffffffffu, ey, d);
        }
        if (lane == 0) {
            const float inv = scalef / s;
            const int v = hV[q];
            const float ox = v ? ex * inv : 0.f;
            const float oy = v ? ey * inv : 0.f;
            out[2 * N + 2 * n]     = hX[q] + ox;
            out[2 * N + 2 * n + 1] = hY[q] + oy;
        }
    }
}

// ---------------------------------------------------------------------------
extern "C" void kernel_launch(void* const* d_in, const int* in_sizes, int n_in,
                              void* d_out, int out_size) {
    const float* mk0 = (const float*)d_in[0];
    const float* mk1 = (const float*)d_in[1];
    const float* f0  = (const float*)d_in[2];
    const float* f1  = (const float*)d_in[3];
    const float* pw  = (const float*)d_in[4];
    const float* pb  = (const float*)d_in[5];
    const int* stridep = (n_in >= 7) ? (const int*)d_in[6] : nullptr;
    float* out = (float*)d_out;

    int N = in_sizes[0] / 2;

    int ngather = (N + 15) / 16;
    int grpsT = (NTPB + 4) / 5;
    int grpsG = (ngather + 1) / 2;
    int grps = grpsT > grpsG ? grpsT : grpsG;
    prep_kernel<<<128 + grps * 7, 256>>>(f1, pw, pb, mk0, f0, stridep, N);

    cudaFuncSetAttribute(corr2_kernel,
                         cudaFuncAttributeMaxDynamicSharedMemorySize, C2_SMEM);
    corr2_kernel<<<(N + CPB - 1) / CPB, 512, C2_SMEM>>>(mk0, mk1, stridep, out, N);
}